// round 4
// baseline (speedup 1.0000x reference)
#include <cuda_runtime.h>
#include <cstdint>

// ---------------- problem constants ----------------
constexpr int Bx   = 2;
constexpr int Hh   = 64;
constexpr int Ww   = 64;
constexpr int Lx   = Hh * Ww;      // 4096
constexpr int CIN  = 96;
constexpr int Dx   = 192;          // INNER
constexpr int NST  = 16;
constexpr int RDT  = 6;
constexpr int KD   = 4;
constexpr int HIDx = 384;
constexpr int NC   = 32;           // scan chunks
constexpr int CHx  = Lx / NC;      // 128 steps per chunk

// ---------------- device scratch (no cudaMalloc allowed) ----------------
__device__ float g_xi   [Bx * Lx * Dx];           // conv input  (B,H,W,D) interleaved
__device__ float g_z    [Bx * Lx * Dx];           // gate
__device__ float g_xs2  [Bx * 2 * Lx * Dx];       // cross-scan dirs 0,1 (flips via index)
__device__ float g_delta[Bx * KD * Lx * Dx];      // (B,K,L,D) scan order
__device__ float g_Bsc  [Bx * KD * Lx * NST];     // (B,K,L,N)
__device__ float g_Csc  [Bx * KD * Lx * NST];
__device__ float g_P    [Bx * KD * NC * Dx * NST];
__device__ float g_He   [Bx * KD * NC * Dx * NST];
__device__ float g_H0   [Bx * KD * NC * Dx * NST];
__device__ float g_y    [Bx * KD * Lx * Dx];      // scan outputs, scan order
__device__ float g_ym   [Bx * Lx * Dx];           // merged * silu(z)
__device__ float g_ob   [Bx * Lx * CIN];          // out (pre-MLP, with residual)
__device__ float g_hid  [Bx * Lx * HIDx];         // mlp hidden

#define DEV_INLINE __device__ __forceinline__

DEV_INLINE float ex2f(float x) { float r; asm("ex2.approx.ftz.f32 %0, %1;" : "=f"(r) : "f"(x)); return r; }
DEV_INLINE float fexp(float x) { return ex2f(x * 1.4426950408889634f); }
DEV_INLINE float fsilu(float x) { return x / (1.f + fexp(-x)); }
DEV_INLINE float fsoftplus(float x) { return (x > 20.f) ? x : log1pf(fexp(x)); }

// ---------------- generic tiled GEMM:  C[M,N] = A[M,K] @ W[N,K]^T  ----------------
// EPI 0: in_proj  -> split to g_xi (c<192) / g_z
// EPI 1: out_proj -> g_ob = C + extra(x residual)        (A = g_ym)
// EPI 2: mlp1     -> g_hid = silu(C + bias)              (A = g_ob)
// EPI 3: mlp2     -> out  = C + bias + g_ob              (A = g_hid)
template <int N, int K, int EPI>
__global__ __launch_bounds__(256) void gemm_k(const float* __restrict__ Aparam,
                                              const float* __restrict__ Wt,
                                              const float* __restrict__ bias,
                                              const float* __restrict__ extra,
                                              float* __restrict__ outp) {
    constexpr int BM = 64, BN = 64, BK = 16;
    __shared__ float As[BK][BM + 4];
    __shared__ float Ws[BK][BN + 4];

    const float* Ap;
    if constexpr (EPI == 0)      Ap = Aparam;
    else if constexpr (EPI == 1) Ap = g_ym;
    else if constexpr (EPI == 2) Ap = g_ob;
    else                         Ap = g_hid;

    int m0 = blockIdx.x * BM;
    int n0 = blockIdx.y * BN;
    int t  = threadIdx.x;
    int tx = t & 15;        // 0..15 -> 4 cols each
    int ty = t >> 4;        // 0..15 -> 4 rows each

    float acc[4][4];
#pragma unroll
    for (int i = 0; i < 4; i++)
#pragma unroll
        for (int j = 0; j < 4; j++) acc[i][j] = 0.f;

    for (int k0 = 0; k0 < K; k0 += BK) {
#pragma unroll
        for (int i = t; i < BM * BK; i += 256) {
            int m = i >> 4, kk = i & 15;
            As[kk][m] = Ap[(m0 + m) * K + k0 + kk];
        }
#pragma unroll
        for (int i = t; i < BN * BK; i += 256) {
            int nn = i >> 4, kk = i & 15;
            int n = n0 + nn;
            Ws[kk][nn] = (n < N) ? Wt[n * K + k0 + kk] : 0.f;
        }
        __syncthreads();
#pragma unroll
        for (int kk = 0; kk < BK; kk++) {
            float4 av = *(const float4*)&As[kk][ty * 4];
            float4 bv = *(const float4*)&Ws[kk][tx * 4];
            float a[4] = {av.x, av.y, av.z, av.w};
            float b[4] = {bv.x, bv.y, bv.z, bv.w};
#pragma unroll
            for (int i = 0; i < 4; i++)
#pragma unroll
                for (int j = 0; j < 4; j++) acc[i][j] = fmaf(a[i], b[j], acc[i][j]);
        }
        __syncthreads();
    }

#pragma unroll
    for (int i = 0; i < 4; i++) {
        int m = m0 + ty * 4 + i;
#pragma unroll
        for (int j = 0; j < 4; j++) {
            int n = n0 + tx * 4 + j;
            if (n >= N) continue;
            float v = acc[i][j];
            if constexpr (EPI == 0) {
                if (n < Dx) g_xi[m * Dx + n] = v;
                else        g_z[m * Dx + (n - Dx)] = v;
            } else if constexpr (EPI == 1) {
                g_ob[m * N + n] = v + extra[m * N + n];
            } else if constexpr (EPI == 2) {
                g_hid[m * N + n] = fsilu(v + bias[n]);
            } else {
                outp[m * N + n] = v + bias[n] + g_ob[m * N + n];
            }
        }
    }
}

// ---------------- depthwise 3x3 conv + bias + silu, write both scan orientations ----------------
__global__ __launch_bounds__(192) void conv_silu_k(const float* __restrict__ cw,
                                                   const float* __restrict__ cb) {
    int l = blockIdx.x;            // 0..L-1 spatial, l = h*W + w
    int b = blockIdx.y;
    int d = threadIdx.x;
    int h = l / Ww, w = l % Ww;

    float acc = cb[d];
    const float* wrow = cw + d * 9;
#pragma unroll
    for (int kh = 0; kh < 3; kh++) {
        int hh = h + kh - 1;
        if (hh < 0 || hh >= Hh) continue;
#pragma unroll
        for (int kw = 0; kw < 3; kw++) {
            int ww2 = w + kw - 1;
            if (ww2 < 0 || ww2 >= Ww) continue;
            acc = fmaf(g_xi[((size_t)b * Lx + hh * Ww + ww2) * Dx + d], wrow[kh * 3 + kw], acc);
        }
    }
    float v = fsilu(acc);
    g_xs2[((size_t)(b * 2 + 0) * Lx + (h * Ww + w)) * Dx + d] = v;
    g_xs2[((size_t)(b * 2 + 1) * Lx + (w * Hh + h)) * Dx + d] = v;
}

// ---------------- x_proj (38xD) + dt (Dx6) + softplus -> delta, Bs, Cs ----------------
constexpr int LT = 32;
__global__ __launch_bounds__(256) void xdbl_k(const float* __restrict__ xpw,
                                              const float* __restrict__ dtw,
                                              const float* __restrict__ dtb) {
    __shared__ float u_sm[LT][Dx + 1];
    __shared__ float xd[RDT + 2 * NST][LT + 1];  // 38 x 33

    int bt = blockIdx.x;
    int lt = bt % (Lx / LT);
    int k  = (bt / (Lx / LT)) % KD;
    int b  = bt / (KD * (Lx / LT));
    int l0 = lt * LT;
    int t  = threadIdx.x;
    int kk2 = k & 1;

    for (int i = t; i < LT * Dx; i += 256) {
        int li = i / Dx, d = i % Dx;
        int l  = l0 + li;
        int lp = (k < 2) ? l : (Lx - 1 - l);
        u_sm[li][d] = g_xs2[((size_t)(b * 2 + kk2) * Lx + lp) * Dx + d];
    }
    __syncthreads();

    constexpr int NCH = RDT + 2 * NST; // 38
    for (int idx = t; idx < NCH * LT; idx += 256) {
        int c = idx >> 5, li = idx & 31;
        const float* wrow = xpw + ((size_t)k * NCH + c) * Dx;
        float s = 0.f;
#pragma unroll 8
        for (int d = 0; d < Dx; d++) s = fmaf(wrow[d], u_sm[li][d], s);
        xd[c][li] = s;
        int gl = l0 + li;
        if (c >= RDT && c < RDT + NST)
            g_Bsc[((size_t)(b * KD + k) * Lx + gl) * NST + (c - RDT)] = s;
        else if (c >= RDT + NST)
            g_Csc[((size_t)(b * KD + k) * Lx + gl) * NST + (c - RDT - NST)] = s;
    }
    __syncthreads();

    for (int idx = t; idx < Dx * LT; idx += 256) {
        int d = idx % Dx, li = idx / Dx;
        float raw = dtb[k * Dx + d];
        const float* wr = dtw + ((size_t)k * Dx + d) * RDT;
#pragma unroll
        for (int r = 0; r < RDT; r++) raw = fmaf(xd[r][li], wr[r], raw);
        g_delta[((size_t)(b * KD + k) * Lx + l0 + li) * Dx + d] = fsoftplus(raw);
    }
}

// ---------------- scan pass A: per-chunk decay product + end state (h0 = 0) ----------------
__global__ __launch_bounds__(192) void scanA_k(const float* __restrict__ A_logs) {
    int blk = blockIdx.x;
    int c = blk % NC;
    int k = (blk / NC) % KD;
    int b = blk / (NC * KD);
    int d = threadIdx.x;
    int l0 = c * CHx;

    __shared__ float Bsm[CHx * NST];
    {
        const float* src = g_Bsc + ((size_t)(b * KD + k) * Lx + l0) * NST;
        for (int i = d; i < CHx * NST; i += 192) Bsm[i] = src[i];
    }

    float Aa[NST], h[NST], P[NST];
#pragma unroll
    for (int n = 0; n < NST; n++) {
        Aa[n] = -fexp(A_logs[((size_t)k * Dx + d) * NST + n]) * 1.4426950408889634f;
        h[n] = 0.f;
        P[n] = 1.f;
    }
    __syncthreads();

    const float* dptr = g_delta + ((size_t)(b * KD + k) * Lx + l0) * Dx + d;
    int lp0 = (k < 2) ? l0 : (Lx - 1 - l0);
    int ust = (k < 2) ? Dx : -Dx;
    const float* uptr = g_xs2 + ((size_t)(b * 2 + (k & 1)) * Lx + lp0) * Dx + d;

    for (int j = 0; j < CHx; j++) {
        float delta = dptr[(size_t)j * Dx];
        float u = *uptr; uptr += ust;
        float du = delta * u;
        float bl[NST];
        *(float4*)(bl + 0)  = *(const float4*)(Bsm + j * NST + 0);
        *(float4*)(bl + 4)  = *(const float4*)(Bsm + j * NST + 4);
        *(float4*)(bl + 8)  = *(const float4*)(Bsm + j * NST + 8);
        *(float4*)(bl + 12) = *(const float4*)(Bsm + j * NST + 12);
#pragma unroll
        for (int n = 0; n < NST; n++) {
            float e = ex2f(delta * Aa[n]);
            h[n] = fmaf(e, h[n], du * bl[n]);
            P[n] *= e;
        }
    }
    size_t base = (((size_t)(b * KD + k) * NC + c) * Dx + d) * NST;
#pragma unroll
    for (int n = 0; n < NST; n++) { g_P[base + n] = P[n]; g_He[base + n] = h[n]; }
}

// ---------------- scan pass B: combine chunks sequentially (tiny) ----------------
__global__ __launch_bounds__(256) void scanB_k() {
    int i = blockIdx.x * 256 + threadIdx.x;   // (bk, d, n)
    int n = i & (NST - 1);
    int d = (i >> 4) % Dx;
    int bk = i / (NST * Dx);
    float h = 0.f;
    for (int c = 0; c < NC; c++) {
        size_t idx = (((size_t)bk * NC + c) * Dx + d) * NST + n;
        g_H0[idx] = h;
        h = fmaf(g_P[idx], h, g_He[idx]);
    }
}

// ---------------- scan pass C: full scan with correct h0, emit y ----------------
__global__ __launch_bounds__(192) void scanC_k(const float* __restrict__ A_logs,
                                               const float* __restrict__ Ds) {
    int blk = blockIdx.x;
    int c = blk % NC;
    int k = (blk / NC) % KD;
    int b = blk / (NC * KD);
    int d = threadIdx.x;
    int l0 = c * CHx;

    __shared__ float Bsm[CHx * NST];
    __shared__ float Csm[CHx * NST];
    {
        const float* sb = g_Bsc + ((size_t)(b * KD + k) * Lx + l0) * NST;
        const float* sc = g_Csc + ((size_t)(b * KD + k) * Lx + l0) * NST;
        for (int i = d; i < CHx * NST; i += 192) { Bsm[i] = sb[i]; Csm[i] = sc[i]; }
    }

    float Aa[NST], h[NST];
    size_t hbase = (((size_t)(b * KD + k) * NC + c) * Dx + d) * NST;
#pragma unroll
    for (int n = 0; n < NST; n++) {
        Aa[n] = -fexp(A_logs[((size_t)k * Dx + d) * NST + n]) * 1.4426950408889634f;
        h[n] = g_H0[hbase + n];
    }
    float Dv = Ds[k * Dx + d];
    __syncthreads();

    const float* dptr = g_delta + ((size_t)(b * KD + k) * Lx + l0) * Dx + d;
    int lp0 = (k < 2) ? l0 : (Lx - 1 - l0);
    int ust = (k < 2) ? Dx : -Dx;
    const float* uptr = g_xs2 + ((size_t)(b * 2 + (k & 1)) * Lx + lp0) * Dx + d;
    float* yptr = g_y + ((size_t)(b * KD + k) * Lx + l0) * Dx + d;

    for (int j = 0; j < CHx; j++) {
        float delta = dptr[(size_t)j * Dx];
        float u = *uptr; uptr += ust;
        float du = delta * u;
        float bl[NST], cl[NST];
        *(float4*)(bl + 0)  = *(const float4*)(Bsm + j * NST + 0);
        *(float4*)(bl + 4)  = *(const float4*)(Bsm + j * NST + 4);
        *(float4*)(bl + 8)  = *(const float4*)(Bsm + j * NST + 8);
        *(float4*)(bl + 12) = *(const float4*)(Bsm + j * NST + 12);
        *(float4*)(cl + 0)  = *(const float4*)(Csm + j * NST + 0);
        *(float4*)(cl + 4)  = *(const float4*)(Csm + j * NST + 4);
        *(float4*)(cl + 8)  = *(const float4*)(Csm + j * NST + 8);
        *(float4*)(cl + 12) = *(const float4*)(Csm + j * NST + 12);
        float acc = 0.f;
#pragma unroll
        for (int n = 0; n < NST; n++) {
            float e = ex2f(delta * Aa[n]);
            h[n] = fmaf(e, h[n], du * bl[n]);
            acc = fmaf(h[n], cl[n], acc);
        }
        yptr[(size_t)j * Dx] = fmaf(Dv, u, acc);
    }
}

// ---------------- cross-merge + gate ----------------
__global__ __launch_bounds__(192) void merge_k() {
    int l = blockIdx.x;               // spatial l = h*W + w
    int b = blockIdx.y;
    int d = threadIdx.x;
    int h = l / Ww, w = l % Ww;
    int lt = w * Hh + h;

    float v = g_y[((size_t)(b * KD + 0) * Lx + l) * Dx + d]
            + g_y[((size_t)(b * KD + 2) * Lx + (Lx - 1 - l)) * Dx + d]
            + g_y[((size_t)(b * KD + 1) * Lx + lt) * Dx + d]
            + g_y[((size_t)(b * KD + 3) * Lx + (Lx - 1 - lt)) * Dx + d];
    float zv = g_z[((size_t)b * Lx + l) * Dx + d];
    g_ym[((size_t)b * Lx + l) * Dx + d] = v * fsilu(zv);
}

// ---------------- launcher ----------------
extern "C" void kernel_launch(void* const* d_in, const int* in_sizes, int n_in,
                              void* d_out, int out_size) {
    const float* x      = (const float*)d_in[0];
    const float* w_in   = (const float*)d_in[1];
    const float* conv_w = (const float*)d_in[2];
    const float* conv_b = (const float*)d_in[3];
    const float* xpw    = (const float*)d_in[4];
    const float* dtw    = (const float*)d_in[5];
    const float* dtb    = (const float*)d_in[6];
    const float* A_logs = (const float*)d_in[7];
    const float* Ds     = (const float*)d_in[8];
    const float* w_out  = (const float*)d_in[9];
    const float* w1     = (const float*)d_in[10];
    const float* b1     = (const float*)d_in[11];
    const float* w2     = (const float*)d_in[12];
    const float* b2     = (const float*)d_in[13];
    float* out = (float*)d_out;

    constexpr int M = Bx * Lx; // 8192

    // 1. in_proj: (M,96)x(384,96)^T -> xi | z
    gemm_k<2 * Dx, CIN, 0><<<dim3(M / 64, (2 * Dx) / 64), 256>>>(x, w_in, nullptr, nullptr, nullptr);
    // 2. depthwise conv + silu -> xs (both orientations)
    conv_silu_k<<<dim3(Lx, Bx), 192>>>(conv_w, conv_b);
    // 3. x_dbl -> delta, Bs, Cs
    xdbl_k<<<Bx * KD * (Lx / LT), 256>>>(xpw, dtw, dtb);
    // 4-6. chunked selective scan
    scanA_k<<<Bx * KD * NC, 192>>>(A_logs);
    scanB_k<<<(Bx * KD * Dx * NST) / 256, 256>>>();
    scanC_k<<<Bx * KD * NC, 192>>>(A_logs, Ds);
    // 7. cross merge + gate
    merge_k<<<dim3(Lx, Bx), 192>>>();
    // 8. out_proj + residual
    gemm_k<CIN, Dx, 1><<<dim3(M / 64, 2), 256>>>(nullptr, w_out, nullptr, x, nullptr);
    // 9. mlp1 + silu
    gemm_k<HIDx, CIN, 2><<<dim3(M / 64, HIDx / 64), 256>>>(nullptr, w1, b1, nullptr, nullptr);
    // 10. mlp2 + residual -> out
    gemm_k<CIN, HIDx, 3><<<dim3(M / 64, 2), 256>>>(nullptr, w2, b2, nullptr, out);

    (void)in_sizes; (void)n_in; (void)out_size;
}